// round 14
// baseline (speedup 1.0000x reference)
#include <cuda_runtime.h>
#include <cuda_fp16.h>
#include <cstdint>
#include <math.h>

// ---------------- problem constants ----------------
#define DIMV   1024
#define HEADS  8
#define HD     128
#define BB     2
#define NN     1024
#define MM     4
#define CL     1024
#define JJ     (MM*CL)          // 4096
#define ZZ     (BB*HEADS)       // 16

// ---------------- scratch pool (static; no runtime alloc) ----------------
constexpr size_t O_KV16 = 0;                      // KV fp16 [8192][2048]  32MB
constexpr size_t O_X16  = O_KV16 + 33554432ull;
constexpr size_t O_C16  = O_X16  + 4194304ull;
constexpr size_t O_WQ   = O_C16  + 16777216ull;
constexpr size_t O_WKV  = O_WQ   + 2097152ull;
constexpr size_t O_WO   = O_WKV  + 4194304ull;
constexpr size_t O_Q16  = O_WO   + 2097152ull;
constexpr size_t O_O16  = O_Q16  + 4194304ull;
constexpr size_t POOLSZ = O_O16  + 4194304ull;

__device__ __align__(1024) unsigned char g_pool[POOLSZ];

// ---------------- helpers ----------------
__device__ __forceinline__ uint32_t smem_u32(const void* p) {
    uint32_t a;
    asm("{ .reg .u64 t; cvta.to.shared.u64 t, %1; cvt.u32.u64 %0, t; }" : "=r"(a) : "l"(p));
    return a;
}
__device__ __forceinline__ void cpa16(uint32_t dst, const void* src) {
    asm volatile("cp.async.cg.shared.global [%0], [%1], 16;" :: "r"(dst), "l"(src));
}
#define CP_COMMIT() asm volatile("cp.async.commit_group;" ::: "memory")
template<int N> __device__ __forceinline__ void cp_wait() {
    asm volatile("cp.async.wait_group %0;" :: "n"(N) : "memory");
}
#define LDSM_X4(r0, r1, r2, r3, a) \
    asm volatile("ldmatrix.sync.aligned.m8n8.x4.shared.b16 {%0,%1,%2,%3}, [%4];" \
                 : "=r"(r0), "=r"(r1), "=r"(r2), "=r"(r3) : "r"(a))
#define LDSM_X4_T(r0, r1, r2, r3, a) \
    asm volatile("ldmatrix.sync.aligned.m8n8.x4.trans.shared.b16 {%0,%1,%2,%3}, [%4];" \
                 : "=r"(r0), "=r"(r1), "=r"(r2), "=r"(r3) : "r"(a))
#define MMA_F16(acc, a, b) \
    asm volatile("mma.sync.aligned.m16n8k16.row.col.f32.f16.f16.f32 " \
                 "{%0,%1,%2,%3}, {%4,%5,%6,%7}, {%8,%9}, {%0,%1,%2,%3};" \
                 : "+f"((acc)[0]), "+f"((acc)[1]), "+f"((acc)[2]), "+f"((acc)[3]) \
                 : "r"((a)[0]), "r"((a)[1]), "r"((a)[2]), "r"((a)[3]), \
                   "r"((b)[0]), "r"((b)[1]))
__device__ __forceinline__ uint32_t packh2(float a, float b) {
    __half2 h = __halves2half2(__float2half_rn(a), __float2half_rn(b));
    return *(uint32_t*)&h;
}
// named barriers for ping-pong groups (id 0 reserved for __syncthreads)
#define BAR_SYNC1() asm volatile("bar.sync 1, 256;" ::: "memory")
#define BAR_SYNC2() asm volatile("bar.sync 2, 256;" ::: "memory")
#define BAR_ARR1()  asm volatile("bar.arrive 1, 256;" ::: "memory")
#define BAR_ARR2()  asm volatile("bar.arrive 2, 256;" ::: "memory")

// ---------------- single segmented fp32 -> fp16 conversion ----------------
#define CV0 524288
#define CV1 (CV0 + 2097152)
#define CV2 (CV1 + 262144)
#define CV3 (CV2 + 524288)
#define CV4 (CV3 + 262144)

__global__ __launch_bounds__(256) void conv_all(
    const float* __restrict__ x,  const float* __restrict__ ctx,
    const float* __restrict__ wq, const float* __restrict__ wkv,
    const float* __restrict__ wo,
    __half* __restrict__ x16, __half* __restrict__ c16,
    __half* __restrict__ wq16, __half* __restrict__ wkv16, __half* __restrict__ wo16)
{
    int i = blockIdx.x * 256 + threadIdx.x;
    if (i >= CV4) return;
    const float* s;  __half* d;  int o;
    if      (i < CV0) { s = x;   d = x16;   o = i; }
    else if (i < CV1) { s = ctx; d = c16;   o = i - CV0; }
    else if (i < CV2) { s = wq;  d = wq16;  o = i - CV1; }
    else if (i < CV3) { s = wkv; d = wkv16; o = i - CV2; }
    else              { s = wo;  d = wo16;  o = i - CV3; }
    float4 v = ((const float4*)s)[o];
    ((__half2*)d)[2 * o]     = __halves2half2(__float2half_rn(v.x), __float2half_rn(v.y));
    ((__half2*)d)[2 * o + 1] = __halves2half2(__float2half_rn(v.z), __float2half_rn(v.w));
}

// ---------------- fused flash attention, ping-pong warp groups ----------------
// grid (NN/128, ZZ) = 128 CTAs, 256 threads (8 warps). Group A = warps 0-3
// (q-rows 0-63), group B = warps 4-7 (q-rows 64-127): every SMSP hosts one
// A-warp and one B-warp. Named barriers stagger the groups so one group's
// softmax runs under the other's HMMAs. 1/32 scale pre-folded into Q.
#define FPITCH 272                     // 17x16B rows, odd -> conflict-free
#define FT64   (64 * FPITCH)           // 17408 B per slot
#define NT     (JJ / 64)               // 64 j-tiles
#define FLASH_SMEM (4 * FT64)          // K slots 0,1; V slots 2,3 (Q staged in 1,3)

__global__ __launch_bounds__(256) void flash_attn(
    const __half* __restrict__ Q,   // [2048][1024], pre-scaled by 1/32
    const __half* __restrict__ KV,  // [8192][2048]
    const float* __restrict__ sims, const float* __restrict__ beta_p,
    __half* __restrict__ O)         // [2048][1024]
{
    extern __shared__ unsigned char smx[];
    const uint32_t sb = smem_u32(smx);
    const int tid = threadIdx.x, wid = tid >> 5, lid = tid & 31;
    const int z = blockIdx.y, zb = z >> 3, zh = z & 7;
    const int row0 = blockIdx.x * 128;
    const float beta = *beta_p;
    const bool grpB = (wid >= 4);

    auto load_kv = [&](int t) {     // K(t)->slot t&1, V(t)->slot 2+(t&1)
        const int j0 = t * 64;
        const uint32_t kbuf = sb + (uint32_t)(t & 1) * FT64;
        const uint32_t vbuf = sb + (uint32_t)(2 + (t & 1)) * FT64;
        const __half* kg = KV + ((size_t)(zb * JJ + j0)) * (2 * DIMV) + zh * HD;
        const __half* vg = kg + DIMV;
        #pragma unroll
        for (int it = 0; it < 4; it++) {
            int c = tid + it * 256, r = c >> 4, cc = c & 15;
            size_t go = (size_t)r * (2 * DIMV) + cc * 8;
            cpa16(kbuf + r * FPITCH + cc * 16, kg + go);
            cpa16(vbuf + r * FPITCH + cc * 16, vg + go);
        }
    };

    // ---- prologue: Q(128 rows) -> slots 1,3 ; K/V(0) -> slots 0,2 ----
    {
        const __half* qg = Q + ((size_t)(zb * NN + row0)) * DIMV + zh * HD;
        #pragma unroll
        for (int it = 0; it < 8; it++) {
            int c = tid + it * 256, r = c >> 4, cc = c & 15;
            uint32_t dst = (r < 64 ? sb + FT64 + (uint32_t)r * FPITCH
                                   : sb + 3u * FT64 + (uint32_t)(r - 64) * FPITCH)
                         + cc * 16;
            cpa16(dst, qg + (size_t)r * DIMV + cc * 8);
        }
        load_kv(0);
        CP_COMMIT();
    }
    cp_wait<0>();
    __syncthreads();

    // ---- Q fragments (then staging slots recycled by K/V(1)) ----
    uint32_t qf[8][4];
    {
        uint32_t qbase = (wid < 4)
            ? sb + FT64     + (uint32_t)(wid * 16 + (lid & 15)) * FPITCH
            : sb + 3u * FT64 + (uint32_t)((wid - 4) * 16 + (lid & 15)) * FPITCH;
        qbase += (lid >> 4) * 16;
        #pragma unroll
        for (int k = 0; k < 8; k++)
            LDSM_X4(qf[k][0], qf[k][1], qf[k][2], qf[k][3], qbase + k * 32);
    }
    __syncthreads();
    if (grpB) BAR_ARR1();          // seed A's first turn

    // K B-frag ([n=j][k=d]); V trans-frag ([k=j][n=d])
    const uint32_t bro = (uint32_t)((lid & 7) + ((lid >> 4) & 1) * 8) * FPITCH
                       + ((lid >> 3) & 1) * 16;
    const uint32_t vro = (uint32_t)((lid & 7) + ((lid >> 3) & 1) * 8) * FPITCH
                       + ((lid >> 4) & 1) * 16;

    float m0 = -INFINITY, m1 = -INFINITY, l0 = 0.f, l1 = 0.f;
    float oacc[16][4];
    #pragma unroll
    for (int t = 0; t < 16; t++)
        #pragma unroll
        for (int r = 0; r < 4; r++) oacc[t][r] = 0.f;

    for (int t = 0; t < NT; t++) {
        if (t + 1 < NT) { load_kv(t + 1); CP_COMMIT(); cp_wait<1>(); }
        else            { cp_wait<0>(); }
        __syncthreads();

        const uint32_t kbuf = sb + (uint32_t)(t & 1) * FT64;
        const uint32_t vbuf = sb + (uint32_t)(2 + (t & 1)) * FT64;
        float sacc[8][4];
        uint32_t pf[8][2];

        auto smma = [&] {
            #pragma unroll
            for (int tt = 0; tt < 8; tt++)
                #pragma unroll
                for (int r = 0; r < 4; r++) sacc[tt][r] = 0.f;
            #pragma unroll
            for (int k = 0; k < 8; k++) {
                #pragma unroll
                for (int j2 = 0; j2 < 4; j2++) {
                    uint32_t b0[2], b1[2];
                    LDSM_X4(b0[0], b0[1], b1[0], b1[1],
                            kbuf + (uint32_t)j2 * (16 * FPITCH) + bro + k * 32);
                    MMA_F16(sacc[j2 * 2],     qf[k], b0);
                    MMA_F16(sacc[j2 * 2 + 1], qf[k], b1);
                }
            }
        };
        auto soft = [&] {
            const float bm = sims[zb * MM + (t >> 4)] * beta;
            float tm0 = -INFINITY, tm1 = -INFINITY;
            #pragma unroll
            for (int tt = 0; tt < 8; tt++) {
                sacc[tt][0] += bm;  sacc[tt][1] += bm;
                sacc[tt][2] += bm;  sacc[tt][3] += bm;
                tm0 = fmaxf(tm0, fmaxf(sacc[tt][0], sacc[tt][1]));
                tm1 = fmaxf(tm1, fmaxf(sacc[tt][2], sacc[tt][3]));
            }
            #pragma unroll
            for (int o = 1; o <= 2; o <<= 1) {
                tm0 = fmaxf(tm0, __shfl_xor_sync(~0u, tm0, o));
                tm1 = fmaxf(tm1, __shfl_xor_sync(~0u, tm1, o));
            }
            const float mn0 = fmaxf(m0, tm0), mn1 = fmaxf(m1, tm1);
            const float c0 = __expf(m0 - mn0), c1 = __expf(m1 - mn1);
            m0 = mn0; m1 = mn1;
            float rs0 = 0.f, rs1 = 0.f;
            #pragma unroll
            for (int tt = 0; tt < 8; tt++) {
                float p0 = __expf(sacc[tt][0] - mn0), p1 = __expf(sacc[tt][1] - mn0);
                float p2 = __expf(sacc[tt][2] - mn1), p3 = __expf(sacc[tt][3] - mn1);
                rs0 += p0 + p1;  rs1 += p2 + p3;
                pf[tt][0] = packh2(p0, p1);
                pf[tt][1] = packh2(p2, p3);
            }
            #pragma unroll
            for (int o = 1; o <= 2; o <<= 1) {
                rs0 += __shfl_xor_sync(~0u, rs0, o);
                rs1 += __shfl_xor_sync(~0u, rs1, o);
            }
            l0 = l0 * c0 + rs0;  l1 = l1 * c1 + rs1;
            #pragma unroll
            for (int tt = 0; tt < 16; tt++) {
                oacc[tt][0] *= c0; oacc[tt][1] *= c0;
                oacc[tt][2] *= c1; oacc[tt][3] *= c1;
            }
        };
        auto pvmma = [&] {
            #pragma unroll
            for (int kk = 0; kk < 4; kk++) {
                uint32_t a[4] = { pf[2 * kk][0], pf[2 * kk][1],
                                  pf[2 * kk + 1][0], pf[2 * kk + 1][1] };
                #pragma unroll
                for (int j2 = 0; j2 < 8; j2++) {
                    uint32_t be[2], bo2[2];
                    LDSM_X4_T(be[0], be[1], bo2[0], bo2[1],
                              vbuf + (uint32_t)kk * (16 * FPITCH) + vro + j2 * 32);
                    MMA_F16(oacc[j2 * 2],     a, be);
                    MMA_F16(oacc[j2 * 2 + 1], a, bo2);
                }
            }
        };

        // ---- ping-pong: tensor pipe alternates A/B while partner does softmax ----
        if (!grpB) {
            BAR_SYNC1();  smma();  BAR_ARR2();
            soft();
            BAR_SYNC1();  pvmma(); BAR_ARR2();
        } else {
            BAR_SYNC2();  smma();  BAR_ARR1();
            soft();
            BAR_SYNC2();  pvmma(); BAR_ARR1();
        }
        __syncthreads();
    }

    // ---- epilogue: normalize, store fp16 ----
    const float i0 = 1.f / l0, i1 = 1.f / l1;
    const int gr0 = row0 + wid * 16 + (lid >> 2);
    #pragma unroll
    for (int t = 0; t < 16; t++) {
        const int d = t * 8 + (lid & 3) * 2;
        __half* o0 = O + ((size_t)(zb * NN + gr0)) * DIMV + zh * HD + d;
        *(__half2*)o0 = __halves2half2(__float2half_rn(oacc[t][0] * i0),
                                       __float2half_rn(oacc[t][1] * i0));
        *(__half2*)(o0 + 8 * DIMV) = __halves2half2(__float2half_rn(oacc[t][2] * i1),
                                                    __float2half_rn(oacc[t][3] * i1));
    }
}

// ---------------- HMMA GEMM (projections): C = A B^T ----------------
// EPI: 1=f32+bias, 4=fp16 (scaled by cscale)
#define PK  40
#define TBUF (128 * PK * 2)
#define STAGEB (2 * TBUF)
#define GEMM_SMEM (2 * STAGEB)  // 40960 B

template<int EPI>
__global__ __launch_bounds__(256) void mma_gemm(
    const __half* __restrict__ A, const __half* __restrict__ B,
    float* __restrict__ Cf, __half* __restrict__ Ch,
    const float* __restrict__ bias, float cscale,
    int Ksz, long long lda, long long ldb, long long ldc)
{
    extern __shared__ unsigned char smx[];
    const uint32_t sb = smem_u32(smx);
    const int tid = threadIdx.x, wid = tid >> 5, lid = tid & 31;
    const int warp_m = wid >> 2, warp_n = wid & 3;
    const int row0 = blockIdx.y * 128, col0 = blockIdx.x * 128;

    float acc[4][4][4];
    #pragma unroll
    for (int i = 0; i < 4; i++)
        #pragma unroll
        for (int j = 0; j < 4; j++)
            #pragma unroll
            for (int r = 0; r < 4; r++) acc[i][j][r] = 0.f;

    const int lr = tid >> 2, lc = tid & 3;
    auto load_stage = [&](int kc, int s) {
        const size_t kb = (size_t)kc * 32;
        const uint32_t st = sb + s * STAGEB;
        #pragma unroll
        for (int it = 0; it < 2; it++) {
            int r = lr + it * 64;
            uint32_t so = (uint32_t)r * 80 + lc * 16;
            cpa16(st + so,        A + (size_t)(row0 + r) * lda + kb + lc * 8);
            cpa16(st + TBUF + so, B + (size_t)(col0 + r) * ldb + kb + lc * 8);
        }
        CP_COMMIT();
    };

    const int nk = Ksz / 32;
    load_stage(0, 0);

    const uint32_t arow = (uint32_t)(warp_m * 64 + (lid & 15)) * 80 + (lid >> 4) * 16;
    const uint32_t brow0 = (uint32_t)(warp_n * 32 + (lid & 7) + ((lid >> 4) & 1) * 8) * 80
                         + ((lid >> 3) & 1) * 16;

    for (int kc = 0; kc < nk; kc++) {
        const int s = kc & 1;
        if (kc + 1 < nk) { load_stage(kc + 1, s ^ 1); cp_wait<1>(); }
        else             { cp_wait<0>(); }
        __syncthreads();
        const uint32_t st = sb + s * STAGEB;
        #pragma unroll
        for (int ks = 0; ks < 2; ks++) {
            uint32_t aa[4][4], bb[4][2];
            #pragma unroll
            for (int i = 0; i < 4; i++)
                LDSM_X4(aa[i][0], aa[i][1], aa[i][2], aa[i][3],
                        st + arow + (uint32_t)i * (16 * 80) + ks * 32);
            #pragma unroll
            for (int j2 = 0; j2 < 2; j2++)
                LDSM_X4(bb[j2*2][0], bb[j2*2][1], bb[j2*2+1][0], bb[j2*2+1][1],
                        st + TBUF + brow0 + (uint32_t)j2 * (16 * 80) + ks * 32);
            #pragma unroll
            for (int i = 0; i < 4; i++)
                #pragma unroll
                for (int j = 0; j < 4; j++)
                    MMA_F16(acc[i][j], aa[i], bb[j]);
        }
        __syncthreads();
    }

    const int qid = lid >> 2, tq = lid & 3;
    #pragma unroll
    for (int i = 0; i < 4; i++) {
        const int gr = row0 + warp_m * 64 + i * 16 + qid;
        #pragma unroll
        for (int j = 0; j < 4; j++) {
            const int gc = col0 + warp_n * 32 + j * 8 + tq * 2;
            size_t off = (size_t)gr * ldc + gc;
            if (EPI == 1) {
                float b0 = bias[gc], b1 = bias[gc + 1];
                float* d0 = Cf + off;  float* d1 = d0 + 8 * ldc;
                d0[0] = acc[i][j][0] + b0;  d0[1] = acc[i][j][1] + b1;
                d1[0] = acc[i][j][2] + b0;  d1[1] = acc[i][j][3] + b1;
            } else {
                #pragma unroll
                for (int half = 0; half < 2; half++)
                    *(__half2*)(Ch + off + (size_t)half * 8 * ldc) =
                        __halves2half2(__float2half_rn(acc[i][j][2*half] * cscale),
                                       __float2half_rn(acc[i][j][2*half+1] * cscale));
            }
        }
    }
}

// ---------------- launch ----------------
extern "C" void kernel_launch(void* const* d_in, const int* in_sizes, int n_in,
                              void* d_out, int out_size)
{
    const float* x        = (const float*)d_in[0];
    const float* context  = (const float*)d_in[1];
    const float* doc_sims = (const float*)d_in[2];
    const float* Wq       = (const float*)d_in[5];
    const float* Wkv      = (const float*)d_in[6];
    const float* beta     = (const float*)d_in[7];
    const float* Wout     = (const float*)d_in[8];
    const float* bout     = (const float*)d_in[9];
    float* out = (float*)d_out;

    unsigned char* pool;
    cudaGetSymbolAddress((void**)&pool, g_pool);
    __half* kv16  = (__half*)(pool + O_KV16);
    __half* x16   = (__half*)(pool + O_X16);
    __half* c16   = (__half*)(pool + O_C16);
    __half* wq16  = (__half*)(pool + O_WQ);
    __half* wkv16 = (__half*)(pool + O_WKV);
    __half* wo16  = (__half*)(pool + O_WO);
    __half* q16   = (__half*)(pool + O_Q16);
    __half* o16   = (__half*)(pool + O_O16);

    cudaFuncSetAttribute(mma_gemm<1>, cudaFuncAttributeMaxDynamicSharedMemorySize, GEMM_SMEM);
    cudaFuncSetAttribute(mma_gemm<4>, cudaFuncAttributeMaxDynamicSharedMemorySize, GEMM_SMEM);
    cudaFuncSetAttribute(flash_attn,  cudaFuncAttributeMaxDynamicSharedMemorySize, FLASH_SMEM);

    conv_all<<<(CV4 + 255) / 256, 256>>>(x, context, Wq, Wkv, Wout,
                                         x16, c16, wq16, wkv16, wo16);

    // 1) Q = (x @ Wq^T) * 1/32 -> fp16 [2048,1024]  (softmax scale pre-folded)
    mma_gemm<4><<<dim3(8, 16), 256, GEMM_SMEM>>>(
        x16, wq16, nullptr, q16, nullptr, 0.03125f, DIMV, DIMV, DIMV, DIMV);

    // 2) KV = ctx @ Wkv^T -> fp16 [8192,2048]
    mma_gemm<4><<<dim3(16, 64), 256, GEMM_SMEM>>>(
        c16, wkv16, nullptr, kv16, nullptr, 1.0f, DIMV, DIMV, DIMV, 2 * DIMV);

    // 3) fused attention (ping-pong warp groups) -> O fp16 [2048,1024]
    flash_attn<<<dim3(NN / 128, ZZ), 256, FLASH_SMEM>>>(
        q16, kv16, doc_sims, beta, o16);

    // 4) out = O @ Wout^T + bout
    mma_gemm<1><<<dim3(8, 16), 256, GEMM_SMEM>>>(
        o16, wo16, out, nullptr, bout, 1.0f, DIMV, DIMV, DIMV, DIMV);
}

// round 15
// speedup vs baseline: 1.0977x; 1.0977x over previous
#include <cuda_runtime.h>
#include <cuda_fp16.h>
#include <cstdint>
#include <math.h>

// ---------------- problem constants ----------------
#define DIMV   1024
#define HEADS  8
#define HD     128
#define BB     2
#define NN     1024
#define MM     4
#define CL     1024
#define JJ     (MM*CL)          // 4096
#define ZZ     (BB*HEADS)       // 16

// ---------------- scratch pool (static; no runtime alloc) ----------------
constexpr size_t O_KV16 = 0;                      // KV fp16 [8192][2048]  32MB
constexpr size_t O_X16  = O_KV16 + 33554432ull;
constexpr size_t O_C16  = O_X16  + 4194304ull;
constexpr size_t O_WQ   = O_C16  + 16777216ull;
constexpr size_t O_WKV  = O_WQ   + 2097152ull;
constexpr size_t O_WO   = O_WKV  + 4194304ull;
constexpr size_t O_Q16  = O_WO   + 2097152ull;
constexpr size_t O_O16  = O_Q16  + 4194304ull;
constexpr size_t POOLSZ = O_O16  + 4194304ull;

__device__ __align__(1024) unsigned char g_pool[POOLSZ];

// ---------------- helpers ----------------
__device__ __forceinline__ uint32_t smem_u32(const void* p) {
    uint32_t a;
    asm("{ .reg .u64 t; cvta.to.shared.u64 t, %1; cvt.u32.u64 %0, t; }" : "=r"(a) : "l"(p));
    return a;
}
__device__ __forceinline__ void cpa16(uint32_t dst, const void* src) {
    asm volatile("cp.async.cg.shared.global [%0], [%1], 16;" :: "r"(dst), "l"(src));
}
#define CP_COMMIT() asm volatile("cp.async.commit_group;" ::: "memory")
template<int N> __device__ __forceinline__ void cp_wait() {
    asm volatile("cp.async.wait_group %0;" :: "n"(N) : "memory");
}
#define LDSM_X4(r0, r1, r2, r3, a) \
    asm volatile("ldmatrix.sync.aligned.m8n8.x4.shared.b16 {%0,%1,%2,%3}, [%4];" \
                 : "=r"(r0), "=r"(r1), "=r"(r2), "=r"(r3) : "r"(a))
#define LDSM_X4_T(r0, r1, r2, r3, a) \
    asm volatile("ldmatrix.sync.aligned.m8n8.x4.trans.shared.b16 {%0,%1,%2,%3}, [%4];" \
                 : "=r"(r0), "=r"(r1), "=r"(r2), "=r"(r3) : "r"(a))
#define MMA_F16(acc, a, b) \
    asm volatile("mma.sync.aligned.m16n8k16.row.col.f32.f16.f16.f32 " \
                 "{%0,%1,%2,%3}, {%4,%5,%6,%7}, {%8,%9}, {%0,%1,%2,%3};" \
                 : "+f"((acc)[0]), "+f"((acc)[1]), "+f"((acc)[2]), "+f"((acc)[3]) \
                 : "r"((a)[0]), "r"((a)[1]), "r"((a)[2]), "r"((a)[3]), \
                   "r"((b)[0]), "r"((b)[1]))
__device__ __forceinline__ uint32_t packh2(float a, float b) {
    __half2 h = __halves2half2(__float2half_rn(a), __float2half_rn(b));
    return *(uint32_t*)&h;
}

// ---------------- single segmented fp32 -> fp16 conversion ----------------
#define CV0 524288
#define CV1 (CV0 + 2097152)
#define CV2 (CV1 + 262144)
#define CV3 (CV2 + 524288)
#define CV4 (CV3 + 262144)

__global__ __launch_bounds__(256) void conv_all(
    const float* __restrict__ x,  const float* __restrict__ ctx,
    const float* __restrict__ wq, const float* __restrict__ wkv,
    const float* __restrict__ wo,
    __half* __restrict__ x16, __half* __restrict__ c16,
    __half* __restrict__ wq16, __half* __restrict__ wkv16, __half* __restrict__ wo16)
{
    int i = blockIdx.x * 256 + threadIdx.x;
    if (i >= CV4) return;
    const float* s;  __half* d;  int o;
    if      (i < CV0) { s = x;   d = x16;   o = i; }
    else if (i < CV1) { s = ctx; d = c16;   o = i - CV0; }
    else if (i < CV2) { s = wq;  d = wq16;  o = i - CV1; }
    else if (i < CV3) { s = wkv; d = wkv16; o = i - CV2; }
    else              { s = wo;  d = wo16;  o = i - CV3; }
    float4 v = ((const float4*)s)[o];
    ((__half2*)d)[2 * o]     = __halves2half2(__float2half_rn(v.x), __float2half_rn(v.y));
    ((__half2*)d)[2 * o + 1] = __halves2half2(__float2half_rn(v.z), __float2half_rn(v.w));
}

// ---------------- fused flash attention (proven R9/R10 config) ----------------
// grid (NN/128, ZZ) = 128 CTAs, 256 threads (8 warps x m16 rows).
// K and V tiles loaded straight from KV rows ([j][d] layout);
// V B-fragments via ldmatrix.trans. Q pre-scaled by 1/32 (fold in Q-GEMM).
#define FPITCH 272                     // bytes/row: 136 halves (17x16B, odd -> conflict-free)
#define FTILE  (128 * FPITCH)          // 34816 B
#define FLASH_SMEM (5 * FTILE)         // Q + 2x(K,V) = 174080 B

__global__ __launch_bounds__(256) void flash_attn(
    const __half* __restrict__ Q,   // [2048][1024], pre-scaled by 1/32
    const __half* __restrict__ KV,  // [8192][2048]
    const float* __restrict__ sims, const float* __restrict__ beta_p,
    __half* __restrict__ O)         // [2048][1024]
{
    extern __shared__ unsigned char smx[];
    const uint32_t sb = smem_u32(smx);
    const int tid = threadIdx.x, wid = tid >> 5, lid = tid & 31;
    const int z = blockIdx.y, zb = z >> 3, zh = z & 7;
    const int row0 = blockIdx.x * 128;
    const float beta = *beta_p;

    // ---- preload Q tile ----
    {
        const __half* qg = Q + ((size_t)(zb * NN + row0)) * DIMV + zh * HD;
        #pragma unroll
        for (int it = 0; it < 8; it++) {
            int c = tid + it * 256, r = c >> 4, cc = c & 15;
            cpa16(sb + r * FPITCH + cc * 16, qg + (size_t)r * DIMV + cc * 8);
        }
        CP_COMMIT();
    }
    auto load_kv = [&](int jt, int s) {
        const int j0 = jt * 128;
        const uint32_t kbuf = sb + FTILE * (1 + 2 * s);
        const uint32_t vbuf = kbuf + FTILE;
        const __half* kg = KV + ((size_t)(zb * JJ + j0)) * (2 * DIMV) + zh * HD;
        const __half* vg = kg + DIMV;          // V columns of the same rows
        #pragma unroll
        for (int it = 0; it < 8; it++) {
            int c = tid + it * 256, r = c >> 4, cc = c & 15;
            size_t go = (size_t)r * (2 * DIMV) + cc * 8;
            cpa16(kbuf + r * FPITCH + cc * 16, kg + go);
            cpa16(vbuf + r * FPITCH + cc * 16, vg + go);
        }
        CP_COMMIT();
    };
    load_kv(0, 0);
    cp_wait<0>();
    __syncthreads();

    // ---- Q fragments (resident across all 32 j-tiles) ----
    uint32_t qf[8][4];
    {
        const uint32_t qrow = (uint32_t)(wid * 16 + (lid & 15)) * FPITCH + (lid >> 4) * 16;
        #pragma unroll
        for (int k = 0; k < 8; k++)
            LDSM_X4(qf[k][0], qf[k][1], qf[k][2], qf[k][3], sb + qrow + k * 32);
    }

    float m0 = -INFINITY, m1 = -INFINITY, l0 = 0.f, l1 = 0.f;
    float oacc[16][4];
    #pragma unroll
    for (int t = 0; t < 16; t++)
        #pragma unroll
        for (int r = 0; r < 4; r++) oacc[t][r] = 0.f;

    // K B-frag addressing ([n=j][k=d]): n rows via bits 0-2,4; k chunk via bit 3
    const uint32_t bro = (uint32_t)((lid & 7) + ((lid >> 4) & 1) * 8) * FPITCH
                       + ((lid >> 3) & 1) * 16;
    // V trans-frag addressing ([k=j][n=d]): k rows via bits 0-2,3; n chunk via bit 4
    const uint32_t vro = (uint32_t)((lid & 7) + ((lid >> 3) & 1) * 8) * FPITCH
                       + ((lid >> 4) & 1) * 16;

    for (int jt = 0; jt < JJ / 128; jt++) {
        const int s = jt & 1;
        if (jt + 1 < JJ / 128) { load_kv(jt + 1, s ^ 1); cp_wait<1>(); }
        else                   { cp_wait<0>(); }
        __syncthreads();

        const uint32_t kbuf = sb + FTILE * (1 + 2 * s);
        const uint32_t vbuf = kbuf + FTILE;

        // ---- S = Q K^T ----
        float sacc[16][4];
        #pragma unroll
        for (int t = 0; t < 16; t++)
            #pragma unroll
            for (int r = 0; r < 4; r++) sacc[t][r] = 0.f;
        #pragma unroll
        for (int k = 0; k < 8; k++) {
            #pragma unroll
            for (int j2 = 0; j2 < 8; j2++) {
                uint32_t b0[2], b1[2];
                LDSM_X4(b0[0], b0[1], b1[0], b1[1],
                        kbuf + (uint32_t)j2 * (16 * FPITCH) + bro + k * 32);
                MMA_F16(sacc[j2 * 2],     qf[k], b0);
                MMA_F16(sacc[j2 * 2 + 1], qf[k], b1);
            }
        }

        // ---- online softmax (rows warp-local; Q pre-scaled so only +bias) ----
        const float bm = sims[zb * MM + (jt >> 3)] * beta;
        float tm0 = -INFINITY, tm1 = -INFINITY;
        #pragma unroll
        for (int t = 0; t < 16; t++) {
            sacc[t][0] += bm;
            sacc[t][1] += bm;
            sacc[t][2] += bm;
            sacc[t][3] += bm;
            tm0 = fmaxf(tm0, fmaxf(sacc[t][0], sacc[t][1]));
            tm1 = fmaxf(tm1, fmaxf(sacc[t][2], sacc[t][3]));
        }
        #pragma unroll
        for (int o = 1; o <= 2; o <<= 1) {
            tm0 = fmaxf(tm0, __shfl_xor_sync(~0u, tm0, o));
            tm1 = fmaxf(tm1, __shfl_xor_sync(~0u, tm1, o));
        }
        const float mn0 = fmaxf(m0, tm0), mn1 = fmaxf(m1, tm1);
        const float c0 = __expf(m0 - mn0), c1 = __expf(m1 - mn1);
        m0 = mn0; m1 = mn1;

        uint32_t pf[16][2];
        float rs0 = 0.f, rs1 = 0.f;
        #pragma unroll
        for (int t = 0; t < 16; t++) {
            float p0 = __expf(sacc[t][0] - mn0), p1 = __expf(sacc[t][1] - mn0);
            float p2 = __expf(sacc[t][2] - mn1), p3 = __expf(sacc[t][3] - mn1);
            rs0 += p0 + p1;  rs1 += p2 + p3;
            pf[t][0] = packh2(p0, p1);
            pf[t][1] = packh2(p2, p3);
        }
        #pragma unroll
        for (int o = 1; o <= 2; o <<= 1) {
            rs0 += __shfl_xor_sync(~0u, rs0, o);
            rs1 += __shfl_xor_sync(~0u, rs1, o);
        }
        l0 = l0 * c0 + rs0;  l1 = l1 * c1 + rs1;
        #pragma unroll
        for (int t = 0; t < 16; t++) {
            oacc[t][0] *= c0; oacc[t][1] *= c0;
            oacc[t][2] *= c1; oacc[t][3] *= c1;
        }

        // ---- O += P V  (V frags via ldmatrix.trans from [j][d] tile) ----
        #pragma unroll
        for (int kk = 0; kk < 8; kk++) {
            uint32_t a[4] = { pf[2 * kk][0], pf[2 * kk][1],
                              pf[2 * kk + 1][0], pf[2 * kk + 1][1] };
            #pragma unroll
            for (int j2 = 0; j2 < 8; j2++) {
                uint32_t be[2], bo2[2];
                LDSM_X4_T(be[0], be[1], bo2[0], bo2[1],
                          vbuf + (uint32_t)kk * (16 * FPITCH) + vro + j2 * 32);
                MMA_F16(oacc[j2 * 2],     a, be);
                MMA_F16(oacc[j2 * 2 + 1], a, bo2);
            }
        }
        __syncthreads();
    }

    // ---- epilogue: normalize, store fp16 ----
    const float i0 = 1.f / l0, i1 = 1.f / l1;
    const int gr0 = row0 + wid * 16 + (lid >> 2);
    #pragma unroll
    for (int t = 0; t < 16; t++) {
        const int d = t * 8 + (lid & 3) * 2;
        __half* o0 = O + ((size_t)(zb * NN + gr0)) * DIMV + zh * HD + d;
        *(__half2*)o0 = __halves2half2(__float2half_rn(oacc[t][0] * i0),
                                       __float2half_rn(oacc[t][1] * i0));
        *(__half2*)(o0 + 8 * DIMV) = __halves2half2(__float2half_rn(oacc[t][2] * i1),
                                                    __float2half_rn(oacc[t][3] * i1));
    }
}

// ---------------- HMMA GEMM (projections): C = A B^T, 3-stage pipeline ----------
// EPI: 1=f32+bias, 4=fp16 (scaled by cscale)
#define PK  40
#define TBUF (128 * PK * 2)
#define STAGEB (2 * TBUF)
#define GSTAGES 3
#define GEMM_SMEM (GSTAGES * STAGEB)  // 61440 B

template<int EPI>
__global__ __launch_bounds__(256) void mma_gemm(
    const __half* __restrict__ A, const __half* __restrict__ B,
    float* __restrict__ Cf, __half* __restrict__ Ch,
    const float* __restrict__ bias, float cscale,
    int Ksz, long long lda, long long ldb, long long ldc)
{
    extern __shared__ unsigned char smx[];
    const uint32_t sb = smem_u32(smx);
    const int tid = threadIdx.x, wid = tid >> 5, lid = tid & 31;
    const int warp_m = wid >> 2, warp_n = wid & 3;
    const int row0 = blockIdx.y * 128, col0 = blockIdx.x * 128;

    float acc[4][4][4];
    #pragma unroll
    for (int i = 0; i < 4; i++)
        #pragma unroll
        for (int j = 0; j < 4; j++)
            #pragma unroll
            for (int r = 0; r < 4; r++) acc[i][j][r] = 0.f;

    const int lr = tid >> 2, lc = tid & 3;
    auto load_stage = [&](int kc) {
        const size_t kb = (size_t)kc * 32;
        const uint32_t st = sb + (uint32_t)(kc % GSTAGES) * STAGEB;
        #pragma unroll
        for (int it = 0; it < 2; it++) {
            int r = lr + it * 64;
            uint32_t so = (uint32_t)r * 80 + lc * 16;
            cpa16(st + so,        A + (size_t)(row0 + r) * lda + kb + lc * 8);
            cpa16(st + TBUF + so, B + (size_t)(col0 + r) * ldb + kb + lc * 8);
        }
        CP_COMMIT();
    };

    const int nk = Ksz / 32;
    load_stage(0);
    if (nk > 1) load_stage(1);

    const uint32_t arow = (uint32_t)(warp_m * 64 + (lid & 15)) * 80 + (lid >> 4) * 16;
    const uint32_t brow0 = (uint32_t)(warp_n * 32 + (lid & 7) + ((lid >> 4) & 1) * 8) * 80
                         + ((lid >> 3) & 1) * 16;

    for (int kc = 0; kc < nk; kc++) {
        // deepest prefetch: slot (kc+2)%3 == slot of kc-1, freed by last iter's sync
        if (kc + 2 < nk) { load_stage(kc + 2); cp_wait<2>(); }
        else if (kc + 1 < nk) { cp_wait<1>(); }
        else { cp_wait<0>(); }
        __syncthreads();

        const uint32_t st = sb + (uint32_t)(kc % GSTAGES) * STAGEB;
        #pragma unroll
        for (int ks = 0; ks < 2; ks++) {
            uint32_t aa[4][4], bb[4][2];
            #pragma unroll
            for (int i = 0; i < 4; i++)
                LDSM_X4(aa[i][0], aa[i][1], aa[i][2], aa[i][3],
                        st + arow + (uint32_t)i * (16 * 80) + ks * 32);
            #pragma unroll
            for (int j2 = 0; j2 < 2; j2++)
                LDSM_X4(bb[j2*2][0], bb[j2*2][1], bb[j2*2+1][0], bb[j2*2+1][1],
                        st + TBUF + brow0 + (uint32_t)j2 * (16 * 80) + ks * 32);
            #pragma unroll
            for (int i = 0; i < 4; i++)
                #pragma unroll
                for (int j = 0; j < 4; j++)
                    MMA_F16(acc[i][j], aa[i], bb[j]);
        }
        __syncthreads();
    }

    const int qid = lid >> 2, tq = lid & 3;
    #pragma unroll
    for (int i = 0; i < 4; i++) {
        const int gr = row0 + warp_m * 64 + i * 16 + qid;
        #pragma unroll
        for (int j = 0; j < 4; j++) {
            const int gc = col0 + warp_n * 32 + j * 8 + tq * 2;
            size_t off = (size_t)gr * ldc + gc;
            if (EPI == 1) {
                float b0 = bias[gc], b1 = bias[gc + 1];
                float* d0 = Cf + off;  float* d1 = d0 + 8 * ldc;
                d0[0] = acc[i][j][0] + b0;  d0[1] = acc[i][j][1] + b1;
                d1[0] = acc[i][j][2] + b0;  d1[1] = acc[i][j][3] + b1;
            } else {
                #pragma unroll
                for (int half = 0; half < 2; half++)
                    *(__half2*)(Ch + off + (size_t)half * 8 * ldc) =
                        __halves2half2(__float2half_rn(acc[i][j][2*half] * cscale),
                                       __float2half_rn(acc[i][j][2*half+1] * cscale));
            }
        }
    }
}

// ---------------- launch ----------------
extern "C" void kernel_launch(void* const* d_in, const int* in_sizes, int n_in,
                              void* d_out, int out_size)
{
    const float* x        = (const float*)d_in[0];
    const float* context  = (const float*)d_in[1];
    const float* doc_sims = (const float*)d_in[2];
    const float* Wq       = (const float*)d_in[5];
    const float* Wkv      = (const float*)d_in[6];
    const float* beta     = (const float*)d_in[7];
    const float* Wout     = (const float*)d_in[8];
    const float* bout     = (const float*)d_in[9];
    float* out = (float*)d_out;

    unsigned char* pool;
    cudaGetSymbolAddress((void**)&pool, g_pool);
    __half* kv16  = (__half*)(pool + O_KV16);
    __half* x16   = (__half*)(pool + O_X16);
    __half* c16   = (__half*)(pool + O_C16);
    __half* wq16  = (__half*)(pool + O_WQ);
    __half* wkv16 = (__half*)(pool + O_WKV);
    __half* wo16  = (__half*)(pool + O_WO);
    __half* q16   = (__half*)(pool + O_Q16);
    __half* o16   = (__half*)(pool + O_O16);

    cudaFuncSetAttribute(mma_gemm<1>, cudaFuncAttributeMaxDynamicSharedMemorySize, GEMM_SMEM);
    cudaFuncSetAttribute(mma_gemm<4>, cudaFuncAttributeMaxDynamicSharedMemorySize, GEMM_SMEM);
    cudaFuncSetAttribute(flash_attn,  cudaFuncAttributeMaxDynamicSharedMemorySize, FLASH_SMEM);

    conv_all<<<(CV4 + 255) / 256, 256>>>(x, context, Wq, Wkv, Wout,
                                         x16, c16, wq16, wkv16, wo16);

    // 1) Q = (x @ Wq^T) * 1/32 -> fp16 [2048,1024]  (softmax scale pre-folded)
    mma_gemm<4><<<dim3(8, 16), 256, GEMM_SMEM>>>(
        x16, wq16, nullptr, q16, nullptr, 0.03125f, DIMV, DIMV, DIMV, DIMV);

    // 2) KV = ctx @ Wkv^T -> fp16 [8192,2048]
    mma_gemm<4><<<dim3(16, 64), 256, GEMM_SMEM>>>(
        c16, wkv16, nullptr, kv16, nullptr, 1.0f, DIMV, DIMV, DIMV, 2 * DIMV);

    // 3) fused attention (proven config) -> O fp16 [2048,1024]
    flash_attn<<<dim3(NN / 128, ZZ), 256, FLASH_SMEM>>>(
        q16, kv16, doc_sims, beta, o16);

    // 4) out = O @ Wout^T + bout
    mma_gemm<1><<<dim3(8, 16), 256, GEMM_SMEM>>>(
        o16, wo16, out, nullptr, bout, 1.0f, DIMV, DIMV, DIMV, DIMV);
}

// round 16
// speedup vs baseline: 1.1502x; 1.0478x over previous
#include <cuda_runtime.h>
#include <cuda_fp16.h>
#include <cstdint>
#include <math.h>

// ---------------- problem constants ----------------
#define DIMV   1024
#define HEADS  8
#define HD     128
#define BB     2
#define NN     1024
#define MM     4
#define CL     1024
#define JJ     (MM*CL)          // 4096
#define ZZ     (BB*HEADS)       // 16

// ---------------- scratch pool (static; no runtime alloc) ----------------
constexpr size_t O_KV16 = 0;                      // KV fp16 [8192][2048]  32MB
constexpr size_t O_X16  = O_KV16 + 33554432ull;
constexpr size_t O_C16  = O_X16  + 4194304ull;
constexpr size_t O_WQ   = O_C16  + 16777216ull;
constexpr size_t O_WKV  = O_WQ   + 2097152ull;
constexpr size_t O_WO   = O_WKV  + 4194304ull;
constexpr size_t O_Q16  = O_WO   + 2097152ull;
constexpr size_t O_O16  = O_Q16  + 4194304ull;
constexpr size_t POOLSZ = O_O16  + 4194304ull;

__device__ __align__(1024) unsigned char g_pool[POOLSZ];

// ---------------- helpers ----------------
__device__ __forceinline__ uint32_t smem_u32(const void* p) {
    uint32_t a;
    asm("{ .reg .u64 t; cvta.to.shared.u64 t, %1; cvt.u32.u64 %0, t; }" : "=r"(a) : "l"(p));
    return a;
}
__device__ __forceinline__ void cpa16(uint32_t dst, const void* src) {
    asm volatile("cp.async.cg.shared.global [%0], [%1], 16;" :: "r"(dst), "l"(src));
}
#define CP_COMMIT() asm volatile("cp.async.commit_group;" ::: "memory")
template<int N> __device__ __forceinline__ void cp_wait() {
    asm volatile("cp.async.wait_group %0;" :: "n"(N) : "memory");
}
#define LDSM_X4(r0, r1, r2, r3, a) \
    asm volatile("ldmatrix.sync.aligned.m8n8.x4.shared.b16 {%0,%1,%2,%3}, [%4];" \
                 : "=r"(r0), "=r"(r1), "=r"(r2), "=r"(r3) : "r"(a))
#define LDSM_X4_T(r0, r1, r2, r3, a) \
    asm volatile("ldmatrix.sync.aligned.m8n8.x4.trans.shared.b16 {%0,%1,%2,%3}, [%4];" \
                 : "=r"(r0), "=r"(r1), "=r"(r2), "=r"(r3) : "r"(a))
#define MMA_F16(acc, a, b) \
    asm volatile("mma.sync.aligned.m16n8k16.row.col.f32.f16.f16.f32 " \
                 "{%0,%1,%2,%3}, {%4,%5,%6,%7}, {%8,%9}, {%0,%1,%2,%3};" \
                 : "+f"((acc)[0]), "+f"((acc)[1]), "+f"((acc)[2]), "+f"((acc)[3]) \
                 : "r"((a)[0]), "r"((a)[1]), "r"((a)[2]), "r"((a)[3]), \
                   "r"((b)[0]), "r"((b)[1]))
__device__ __forceinline__ uint32_t packh2(float a, float b) {
    __half2 h = __halves2half2(__float2half_rn(a), __float2half_rn(b));
    return *(uint32_t*)&h;
}

// ---------------- single segmented fp32 -> fp16 conversion ----------------
#define CV0 524288
#define CV1 (CV0 + 2097152)
#define CV2 (CV1 + 262144)
#define CV3 (CV2 + 524288)
#define CV4 (CV3 + 262144)

__global__ __launch_bounds__(256) void conv_all(
    const float* __restrict__ x,  const float* __restrict__ ctx,
    const float* __restrict__ wq, const float* __restrict__ wkv,
    const float* __restrict__ wo,
    __half* __restrict__ x16, __half* __restrict__ c16,
    __half* __restrict__ wq16, __half* __restrict__ wkv16, __half* __restrict__ wo16)
{
    int i = blockIdx.x * 256 + threadIdx.x;
    if (i >= CV4) return;
    const float* s;  __half* d;  int o;
    if      (i < CV0) { s = x;   d = x16;   o = i; }
    else if (i < CV1) { s = ctx; d = c16;   o = i - CV0; }
    else if (i < CV2) { s = wq;  d = wq16;  o = i - CV1; }
    else if (i < CV3) { s = wkv; d = wkv16; o = i - CV2; }
    else              { s = wo;  d = wo16;  o = i - CV3; }
    float4 v = ((const float4*)s)[o];
    ((__half2*)d)[2 * o]     = __halves2half2(__float2half_rn(v.x), __float2half_rn(v.y));
    ((__half2*)d)[2 * o + 1] = __halves2half2(__float2half_rn(v.z), __float2half_rn(v.w));
}

// ---------------- fused flash attention (proven config) ----------------
#define FPITCH 272                     // bytes/row: 136 halves (17x16B, odd -> conflict-free)
#define FTILE  (128 * FPITCH)          // 34816 B
#define FLASH_SMEM (5 * FTILE)         // Q + 2x(K,V) = 174080 B

__global__ __launch_bounds__(256) void flash_attn(
    const __half* __restrict__ Q,   // [2048][1024], pre-scaled by 1/32
    const __half* __restrict__ KV,  // [8192][2048]
    const float* __restrict__ sims, const float* __restrict__ beta_p,
    __half* __restrict__ O)         // [2048][1024]
{
    extern __shared__ unsigned char smx[];
    const uint32_t sb = smem_u32(smx);
    const int tid = threadIdx.x, wid = tid >> 5, lid = tid & 31;
    const int z = blockIdx.y, zb = z >> 3, zh = z & 7;
    const int row0 = blockIdx.x * 128;
    const float beta = *beta_p;

    {
        const __half* qg = Q + ((size_t)(zb * NN + row0)) * DIMV + zh * HD;
        #pragma unroll
        for (int it = 0; it < 8; it++) {
            int c = tid + it * 256, r = c >> 4, cc = c & 15;
            cpa16(sb + r * FPITCH + cc * 16, qg + (size_t)r * DIMV + cc * 8);
        }
        CP_COMMIT();
    }
    auto load_kv = [&](int jt, int s) {
        const int j0 = jt * 128;
        const uint32_t kbuf = sb + FTILE * (1 + 2 * s);
        const uint32_t vbuf = kbuf + FTILE;
        const __half* kg = KV + ((size_t)(zb * JJ + j0)) * (2 * DIMV) + zh * HD;
        const __half* vg = kg + DIMV;
        #pragma unroll
        for (int it = 0; it < 8; it++) {
            int c = tid + it * 256, r = c >> 4, cc = c & 15;
            size_t go = (size_t)r * (2 * DIMV) + cc * 8;
            cpa16(kbuf + r * FPITCH + cc * 16, kg + go);
            cpa16(vbuf + r * FPITCH + cc * 16, vg + go);
        }
        CP_COMMIT();
    };
    load_kv(0, 0);
    cp_wait<0>();
    __syncthreads();

    uint32_t qf[8][4];
    {
        const uint32_t qrow = (uint32_t)(wid * 16 + (lid & 15)) * FPITCH + (lid >> 4) * 16;
        #pragma unroll
        for (int k = 0; k < 8; k++)
            LDSM_X4(qf[k][0], qf[k][1], qf[k][2], qf[k][3], sb + qrow + k * 32);
    }

    float m0 = -INFINITY, m1 = -INFINITY, l0 = 0.f, l1 = 0.f;
    float oacc[16][4];
    #pragma unroll
    for (int t = 0; t < 16; t++)
        #pragma unroll
        for (int r = 0; r < 4; r++) oacc[t][r] = 0.f;

    const uint32_t bro = (uint32_t)((lid & 7) + ((lid >> 4) & 1) * 8) * FPITCH
                       + ((lid >> 3) & 1) * 16;
    const uint32_t vro = (uint32_t)((lid & 7) + ((lid >> 3) & 1) * 8) * FPITCH
                       + ((lid >> 4) & 1) * 16;

    for (int jt = 0; jt < JJ / 128; jt++) {
        const int s = jt & 1;
        if (jt + 1 < JJ / 128) { load_kv(jt + 1, s ^ 1); cp_wait<1>(); }
        else                   { cp_wait<0>(); }
        __syncthreads();

        const uint32_t kbuf = sb + FTILE * (1 + 2 * s);
        const uint32_t vbuf = kbuf + FTILE;

        float sacc[16][4];
        #pragma unroll
        for (int t = 0; t < 16; t++)
            #pragma unroll
            for (int r = 0; r < 4; r++) sacc[t][r] = 0.f;
        #pragma unroll
        for (int k = 0; k < 8; k++) {
            #pragma unroll
            for (int j2 = 0; j2 < 8; j2++) {
                uint32_t b0[2], b1[2];
                LDSM_X4(b0[0], b0[1], b1[0], b1[1],
                        kbuf + (uint32_t)j2 * (16 * FPITCH) + bro + k * 32);
                MMA_F16(sacc[j2 * 2],     qf[k], b0);
                MMA_F16(sacc[j2 * 2 + 1], qf[k], b1);
            }
        }

        const float bm = sims[zb * MM + (jt >> 3)] * beta;
        float tm0 = -INFINITY, tm1 = -INFINITY;
        #pragma unroll
        for (int t = 0; t < 16; t++) {
            sacc[t][0] += bm;
            sacc[t][1] += bm;
            sacc[t][2] += bm;
            sacc[t][3] += bm;
            tm0 = fmaxf(tm0, fmaxf(sacc[t][0], sacc[t][1]));
            tm1 = fmaxf(tm1, fmaxf(sacc[t][2], sacc[t][3]));
        }
        #pragma unroll
        for (int o = 1; o <= 2; o <<= 1) {
            tm0 = fmaxf(tm0, __shfl_xor_sync(~0u, tm0, o));
            tm1 = fmaxf(tm1, __shfl_xor_sync(~0u, tm1, o));
        }
        const float mn0 = fmaxf(m0, tm0), mn1 = fmaxf(m1, tm1);
        const float c0 = __expf(m0 - mn0), c1 = __expf(m1 - mn1);
        m0 = mn0; m1 = mn1;

        uint32_t pf[16][2];
        float rs0 = 0.f, rs1 = 0.f;
        #pragma unroll
        for (int t = 0; t < 16; t++) {
            float p0 = __expf(sacc[t][0] - mn0), p1 = __expf(sacc[t][1] - mn0);
            float p2 = __expf(sacc[t][2] - mn1), p3 = __expf(sacc[t][3] - mn1);
            rs0 += p0 + p1;  rs1 += p2 + p3;
            pf[t][0] = packh2(p0, p1);
            pf[t][1] = packh2(p2, p3);
        }
        #pragma unroll
        for (int o = 1; o <= 2; o <<= 1) {
            rs0 += __shfl_xor_sync(~0u, rs0, o);
            rs1 += __shfl_xor_sync(~0u, rs1, o);
        }
        l0 = l0 * c0 + rs0;  l1 = l1 * c1 + rs1;
        #pragma unroll
        for (int t = 0; t < 16; t++) {
            oacc[t][0] *= c0; oacc[t][1] *= c0;
            oacc[t][2] *= c1; oacc[t][3] *= c1;
        }

        #pragma unroll
        for (int kk = 0; kk < 8; kk++) {
            uint32_t a[4] = { pf[2 * kk][0], pf[2 * kk][1],
                              pf[2 * kk + 1][0], pf[2 * kk + 1][1] };
            #pragma unroll
            for (int j2 = 0; j2 < 8; j2++) {
                uint32_t be[2], bo2[2];
                LDSM_X4_T(be[0], be[1], bo2[0], bo2[1],
                          vbuf + (uint32_t)kk * (16 * FPITCH) + vro + j2 * 32);
                MMA_F16(oacc[j2 * 2],     a, be);
                MMA_F16(oacc[j2 * 2 + 1], a, bo2);
            }
        }
        __syncthreads();
    }

    const float i0 = 1.f / l0, i1 = 1.f / l1;
    const int gr0 = row0 + wid * 16 + (lid >> 2);
    #pragma unroll
    for (int t = 0; t < 16; t++) {
        const int d = t * 8 + (lid & 3) * 2;
        __half* o0 = O + ((size_t)(zb * NN + gr0)) * DIMV + zh * HD + d;
        *(__half2*)o0 = __halves2half2(__float2half_rn(oacc[t][0] * i0),
                                       __float2half_rn(oacc[t][1] * i0));
        *(__half2*)(o0 + 8 * DIMV) = __halves2half2(__float2half_rn(oacc[t][2] * i1),
                                                    __float2half_rn(oacc[t][3] * i1));
    }
}

// ---------------- GEMM cores (3-stage pipelined) ----------------
#define PK  40
#define TBUF (128 * PK * 2)
#define STAGEB (2 * TBUF)
#define GSTAGES 3
#define GEMM_SMEM (GSTAGES * STAGEB)  // 61440 B

// inner body shared by both GEMM kernels
template<int EPI>   // 1=f32+bias, 4=fp16*cscale
__device__ __forceinline__ void gemm_body(
    const __half* __restrict__ A, const __half* __restrict__ B,
    float* __restrict__ Cf, __half* __restrict__ Ch,
    const float* __restrict__ bias, float cscale,
    int Ksz, long long lda, long long ldb, long long ldc,
    int row0, int col0, uint32_t sb)
{
    const int tid = threadIdx.x, wid = tid >> 5, lid = tid & 31;
    const int warp_m = wid >> 2, warp_n = wid & 3;

    float acc[4][4][4];
    #pragma unroll
    for (int i = 0; i < 4; i++)
        #pragma unroll
        for (int j = 0; j < 4; j++)
            #pragma unroll
            for (int r = 0; r < 4; r++) acc[i][j][r] = 0.f;

    const int lr = tid >> 2, lc = tid & 3;
    auto load_stage = [&](int kc) {
        const size_t kb = (size_t)kc * 32;
        const uint32_t st = sb + (uint32_t)(kc % GSTAGES) * STAGEB;
        #pragma unroll
        for (int it = 0; it < 2; it++) {
            int r = lr + it * 64;
            uint32_t so = (uint32_t)r * 80 + lc * 16;
            cpa16(st + so,        A + (size_t)(row0 + r) * lda + kb + lc * 8);
            cpa16(st + TBUF + so, B + (size_t)(col0 + r) * ldb + kb + lc * 8);
        }
        CP_COMMIT();
    };

    const int nk = Ksz / 32;
    load_stage(0);
    if (nk > 1) load_stage(1);

    const uint32_t arow = (uint32_t)(warp_m * 64 + (lid & 15)) * 80 + (lid >> 4) * 16;
    const uint32_t brow0 = (uint32_t)(warp_n * 32 + (lid & 7) + ((lid >> 4) & 1) * 8) * 80
                         + ((lid >> 3) & 1) * 16;

    for (int kc = 0; kc < nk; kc++) {
        if (kc + 2 < nk) { load_stage(kc + 2); cp_wait<2>(); }
        else if (kc + 1 < nk) { cp_wait<1>(); }
        else { cp_wait<0>(); }
        __syncthreads();

        const uint32_t st = sb + (uint32_t)(kc % GSTAGES) * STAGEB;
        #pragma unroll
        for (int ks = 0; ks < 2; ks++) {
            uint32_t aa[4][4], bb[4][2];
            #pragma unroll
            for (int i = 0; i < 4; i++)
                LDSM_X4(aa[i][0], aa[i][1], aa[i][2], aa[i][3],
                        st + arow + (uint32_t)i * (16 * 80) + ks * 32);
            #pragma unroll
            for (int j2 = 0; j2 < 2; j2++)
                LDSM_X4(bb[j2*2][0], bb[j2*2][1], bb[j2*2+1][0], bb[j2*2+1][1],
                        st + TBUF + brow0 + (uint32_t)j2 * (16 * 80) + ks * 32);
            #pragma unroll
            for (int i = 0; i < 4; i++)
                #pragma unroll
                for (int j = 0; j < 4; j++)
                    MMA_F16(acc[i][j], aa[i], bb[j]);
        }
        __syncthreads();
    }

    const int qid = lid >> 2, tq = lid & 3;
    #pragma unroll
    for (int i = 0; i < 4; i++) {
        const int gr = row0 + warp_m * 64 + i * 16 + qid;
        #pragma unroll
        for (int j = 0; j < 4; j++) {
            const int gc = col0 + warp_n * 32 + j * 8 + tq * 2;
            size_t off = (size_t)gr * ldc + gc;
            if (EPI == 1) {
                float b0 = bias[gc], b1 = bias[gc + 1];
                float* d0 = Cf + off;  float* d1 = d0 + 8 * ldc;
                d0[0] = acc[i][j][0] + b0;  d0[1] = acc[i][j][1] + b1;
                d1[0] = acc[i][j][2] + b0;  d1[1] = acc[i][j][3] + b1;
            } else {
                #pragma unroll
                for (int half = 0; half < 2; half++)
                    *(__half2*)(Ch + off + (size_t)half * 8 * ldc) =
                        __halves2half2(__float2half_rn(acc[i][j][2*half] * cscale),
                                       __float2half_rn(acc[i][j][2*half+1] * cscale));
            }
        }
    }
}

// merged Q + KV projection: flat grid, blocks 0..1023 = KV, 1024..1151 = Q
#define QKV_BLOCKS (1024 + 128)

__global__ __launch_bounds__(256) void mma_gemm_qkv(
    const __half* __restrict__ x16,  const __half* __restrict__ wq16,
    const __half* __restrict__ c16,  const __half* __restrict__ wkv16,
    __half* __restrict__ q16, __half* __restrict__ kv16)
{
    extern __shared__ unsigned char smx[];
    const uint32_t sb = smem_u32(smx);
    const int bid = blockIdx.x;
    if (bid < 1024) {
        // KV = ctx @ Wkv^T : grid 16 x 64 tiles
        const int bx = bid & 15, by = bid >> 4;
        gemm_body<4>(c16, wkv16, nullptr, kv16, nullptr, 1.0f,
                     DIMV, DIMV, DIMV, 2 * DIMV, by * 128, bx * 128, sb);
    } else {
        // Q = (x @ Wq^T) * 1/32 : grid 8 x 16 tiles
        const int id = bid - 1024;
        const int bx = id & 7, by = id >> 3;
        gemm_body<4>(x16, wq16, nullptr, q16, nullptr, 0.03125f,
                     DIMV, DIMV, DIMV, DIMV, by * 128, bx * 128, sb);
    }
}

// out projection (f32 + bias)
__global__ __launch_bounds__(256) void mma_gemm_out(
    const __half* __restrict__ A, const __half* __restrict__ B,
    float* __restrict__ Cf, const float* __restrict__ bias)
{
    extern __shared__ unsigned char smx[];
    const uint32_t sb = smem_u32(smx);
    gemm_body<1>(A, B, Cf, nullptr, bias, 1.0f,
                 DIMV, DIMV, DIMV, DIMV, blockIdx.y * 128, blockIdx.x * 128, sb);
}

// ---------------- launch ----------------
extern "C" void kernel_launch(void* const* d_in, const int* in_sizes, int n_in,
                              void* d_out, int out_size)
{
    const float* x        = (const float*)d_in[0];
    const float* context  = (const float*)d_in[1];
    const float* doc_sims = (const float*)d_in[2];
    const float* Wq       = (const float*)d_in[5];
    const float* Wkv      = (const float*)d_in[6];
    const float* beta     = (const float*)d_in[7];
    const float* Wout     = (const float*)d_in[8];
    const float* bout     = (const float*)d_in[9];
    float* out = (float*)d_out;

    unsigned char* pool;
    cudaGetSymbolAddress((void**)&pool, g_pool);
    __half* kv16  = (__half*)(pool + O_KV16);
    __half* x16   = (__half*)(pool + O_X16);
    __half* c16   = (__half*)(pool + O_C16);
    __half* wq16  = (__half*)(pool + O_WQ);
    __half* wkv16 = (__half*)(pool + O_WKV);
    __half* wo16  = (__half*)(pool + O_WO);
    __half* q16   = (__half*)(pool + O_Q16);
    __half* o16   = (__half*)(pool + O_O16);

    cudaFuncSetAttribute(mma_gemm_qkv, cudaFuncAttributeMaxDynamicSharedMemorySize, GEMM_SMEM);
    cudaFuncSetAttribute(mma_gemm_out, cudaFuncAttributeMaxDynamicSharedMemorySize, GEMM_SMEM);
    cudaFuncSetAttribute(flash_attn,   cudaFuncAttributeMaxDynamicSharedMemorySize, FLASH_SMEM);

    // all fp32 -> fp16 conversions in one launch
    conv_all<<<(CV4 + 255) / 256, 256>>>(x, context, Wq, Wkv, Wout,
                                         x16, c16, wq16, wkv16, wo16);

    // 1+2) merged Q & KV projections (one 1152-CTA launch, no Q wave quantization)
    mma_gemm_qkv<<<QKV_BLOCKS, 256, GEMM_SMEM>>>(x16, wq16, c16, wkv16, q16, kv16);

    // 3) fused attention -> O fp16 [2048,1024]
    flash_attn<<<dim3(NN / 128, ZZ), 256, FLASH_SMEM>>>(
        q16, kv16, doc_sims, beta, o16);

    // 4) out = O @ Wout^T + bout
    mma_gemm_out<<<dim3(8, 16), 256, GEMM_SMEM>>>(o16, wo16, out, bout);
}